// round 8
// baseline (speedup 1.0000x reference)
#include <cuda_runtime.h>
#include <cuda_bf16.h>
#include <math.h>
#include <stdint.h>

#define NN   50000
#define EE   800000
#define DIN  256
#define DH   128

// ---------------- scratch (static device globals; no allocation) ----------------
__device__ __align__(16) __nv_bfloat16 g_C1b[(size_t)NN * 384];   // bf16: msg | r0 | proj
__device__ __align__(16) __nv_bfloat16 g_C2b[(size_t)NN * 256];   // bf16: msg | r1
__device__ __align__(16) __nv_bfloat16 g_xb [(size_t)NN * DIN];   // x in bf16
__device__ __align__(16) __nv_bfloat16 g_h1b[(size_t)NN * DH];    // h1 in bf16
__device__ __align__(16) __nv_bfloat16 g_h2b[(size_t)NN * DH];    // h2 in bf16
__device__ int g_deg[NN];
__device__ int g_rowptr[NN + 1];
__device__ int g_cursor[NN];
__device__ int g_csr_src[EE];
__device__ int g_bsum[64];
__device__ __align__(16) uint32_t g_Bp1b[(DIN / 2) * 384];        // bf16 pairs [kpair][384]
__device__ __align__(16) uint32_t g_Bp2b[(DH / 2) * 256];         // bf16 pairs [kpair][256]

// ---------------- side-stream resources ----------------
static cudaStream_t g_s2 = nullptr;
static cudaEvent_t  g_evFork = nullptr, g_evJoin = nullptr;
namespace {
struct InitRes {
    InitRes() {
        cudaStreamCreateWithFlags(&g_s2, cudaStreamNonBlocking);
        cudaEventCreateWithFlags(&g_evFork, cudaEventDisableTiming);
        cudaEventCreateWithFlags(&g_evJoin, cudaEventDisableTiming);
    }
};
static InitRes g_initres;
}

// ---------------- pack weights to bf16 k-pair layout ----------------
__global__ void pack_kernel(const float* __restrict__ Wl0, const float* __restrict__ Wr0,
                            const float* __restrict__ Wp,
                            const float* __restrict__ Wl1, const float* __restrict__ Wr1) {
    int idx = blockIdx.x * blockDim.x + threadIdx.x;
    if (idx < (DIN / 2) * 384) {
        int kp = idx / 384, j = idx % 384;
        int k0 = 2 * kp, k1 = 2 * kp + 1;
        float lo, hi;
        if (j < 128)      { lo = Wl0[k0 * DH + j];        hi = Wl0[k1 * DH + j]; }
        else if (j < 256) { lo = Wr0[k0 * DH + j - 128];  hi = Wr0[k1 * DH + j - 128]; }
        else              { lo = Wp [k0 * DH + j - 256];  hi = Wp [k1 * DH + j - 256]; }
        __nv_bfloat162 p = __floats2bfloat162_rn(lo, hi);
        g_Bp1b[idx] = *reinterpret_cast<uint32_t*>(&p);
    }
    if (idx < (DH / 2) * 256) {
        int kp = idx / 256, j = idx % 256;
        int k0 = 2 * kp, k1 = 2 * kp + 1;
        float lo, hi;
        if (j < 128) { lo = Wl1[k0 * DH + j];       hi = Wl1[k1 * DH + j]; }
        else         { lo = Wr1[k0 * DH + j - 128]; hi = Wr1[k1 * DH + j - 128]; }
        __nv_bfloat162 p = __floats2bfloat162_rn(lo, hi);
        g_Bp2b[idx] = *reinterpret_cast<uint32_t*>(&p);
    }
}

// ---------------- x -> bf16 ----------------
__global__ void convert_x(const float* __restrict__ x, int nWords) {
    int i = blockIdx.x * blockDim.x + threadIdx.x;
    if (i >= nWords) return;
    float2 v = ((const float2*)x)[i];
    __nv_bfloat162 p = __floats2bfloat162_rn(v.x, v.y);
    ((uint32_t*)g_xb)[i] = *reinterpret_cast<uint32_t*>(&p);
}

// ---------------- CSR build chain (side stream) ----------------
__global__ void zero_deg(int N) {
    int i = blockIdx.x * blockDim.x + threadIdx.x;
    if (i < N) g_deg[i] = 0;
}

__global__ void hist_kernel(const int* __restrict__ dst, int E) {
    int e = blockIdx.x * blockDim.x + threadIdx.x;
    if (e < E) atomicAdd(&g_deg[dst[e]], 1);
}

__global__ __launch_bounds__(1024)
void scan_blocks(int N) {
    __shared__ int wsum[32];
    int lane = threadIdx.x & 31, wid = threadIdx.x >> 5;
    int idx = blockIdx.x * 1024 + threadIdx.x;
    int v = (idx < N) ? g_deg[idx] : 0;
    int x = v;
#pragma unroll
    for (int o = 1; o < 32; o <<= 1) {
        int y = __shfl_up_sync(0xffffffffu, x, o);
        if (lane >= o) x += y;
    }
    if (lane == 31) wsum[wid] = x;
    __syncthreads();
    if (wid == 0) {
        int s = wsum[lane];
#pragma unroll
        for (int o = 1; o < 32; o <<= 1) {
            int y = __shfl_up_sync(0xffffffffu, s, o);
            if (lane >= o) s += y;
        }
        wsum[lane] = s;
    }
    __syncthreads();
    int excl = x - v + (wid > 0 ? wsum[wid - 1] : 0);
    if (idx < N) g_rowptr[idx] = excl;
    if (threadIdx.x == 1023) g_bsum[blockIdx.x] = excl + v;
}

__global__ void scan_add_fused(int N) {
    __shared__ int pre_s;
    int grp = blockIdx.x >> 2;
    if (threadIdx.x < 32) {
        int s = 0;
        for (int g = threadIdx.x; g < grp; g += 32) s += g_bsum[g];
#pragma unroll
        for (int o = 16; o; o >>= 1) s += __shfl_xor_sync(0xffffffffu, s, o);
        if (threadIdx.x == 0) pre_s = s;
    }
    __syncthreads();
    int i = blockIdx.x * 256 + threadIdx.x;
    if (i < N) {
        int r = g_rowptr[i] + pre_s;
        g_rowptr[i] = r;
        g_cursor[i] = r;
        if (i == N - 1) g_rowptr[N] = r + g_deg[N - 1];
    }
}

__global__ void csr_fill(const int* __restrict__ src, const int* __restrict__ dst, int E) {
    int e = blockIdx.x * blockDim.x + threadIdx.x;
    if (e >= E) return;
    int slot = atomicAdd(&g_cursor[dst[e]], 1);
    g_csr_src[slot] = src[e];
}

// ---------------- bf16 tensor-core GEMM (m16n8k16), bf16 output ----------------
#define SPAD 136

__device__ __forceinline__ void mma_bf16(float c[4], uint32_t a0, uint32_t a1,
                                         uint32_t a2, uint32_t a3,
                                         uint32_t b0, uint32_t b1) {
    asm volatile(
        "mma.sync.aligned.m16n8k16.row.col.f32.bf16.bf16.f32 "
        "{%0,%1,%2,%3}, {%4,%5,%6,%7}, {%8,%9}, {%0,%1,%2,%3};"
        : "+f"(c[0]), "+f"(c[1]), "+f"(c[2]), "+f"(c[3])
        : "r"(a0), "r"(a1), "r"(a2), "r"(a3), "r"(b0), "r"(b1));
}

__global__ __launch_bounds__(256)
void gemm_bf16(const __nv_bfloat16* __restrict__ A, const uint32_t* __restrict__ Bp,
               __nv_bfloat16* __restrict__ Cb, int M, int K, int Ncol) {
    __shared__ uint32_t As[16][SPAD];
    __shared__ uint32_t Bs[16][SPAD];

    const int t = threadIdx.x;
    const int lane = t & 31;
    const int warp = t >> 5;
    const int wm = (warp & 1) * 64;
    const int wn = (warp >> 1) * 32;
    const int g = lane >> 2;
    const int t4 = lane & 3;

    const int rowBase = blockIdx.y * 128;
    const int colBase = blockIdx.x * 128;

    const int ar = t & 127;
    const int ah = t >> 7;
    const int bkp = t >> 4;
    const int bcol = (t & 15) * 8;

    float acc[4][4][4];
#pragma unroll
    for (int mt = 0; mt < 4; mt++)
#pragma unroll
        for (int nt = 0; nt < 4; nt++)
#pragma unroll
            for (int i = 0; i < 4; i++) acc[mt][nt][i] = 0.f;

    const int grow = rowBase + ar;
    const bool arow_ok = (grow < M);
    const __nv_bfloat16* aBase = A + (size_t)grow * K + ah * 16;
    const uint32_t* bBase = Bp + (size_t)bkp * Ncol + colBase + bcol;

    uint4 ra0, ra1, rb0, rb1;

    if (arow_ok) {
        ra0 = *(const uint4*)(aBase);
        ra1 = *(const uint4*)(aBase + 8);
    } else {
        ra0 = make_uint4(0, 0, 0, 0); ra1 = make_uint4(0, 0, 0, 0);
    }
    rb0 = *(const uint4*)(bBase);
    rb1 = *(const uint4*)(bBase + 4);

    const int nChunks = K >> 5;
    for (int ci = 0; ci < nChunks; ci++) {
        {
            const int kb = ah * 8;
            As[kb + 0][ar] = ra0.x; As[kb + 1][ar] = ra0.y;
            As[kb + 2][ar] = ra0.z; As[kb + 3][ar] = ra0.w;
            As[kb + 4][ar] = ra1.x; As[kb + 5][ar] = ra1.y;
            As[kb + 6][ar] = ra1.z; As[kb + 7][ar] = ra1.w;
            *(uint4*)&Bs[bkp][bcol]     = rb0;
            *(uint4*)&Bs[bkp][bcol + 4] = rb1;
        }
        __syncthreads();

        if (ci + 1 < nChunks) {
            int k0 = (ci + 1) << 5;
            if (arow_ok) {
                ra0 = *(const uint4*)(aBase + k0);
                ra1 = *(const uint4*)(aBase + k0 + 8);
            }
            rb0 = *(const uint4*)(bBase + (size_t)(k0 >> 1) * Ncol);
            rb1 = *(const uint4*)(bBase + (size_t)(k0 >> 1) * Ncol + 4);
        }

#pragma unroll
        for (int kk = 0; kk < 2; kk++) {
            const int kb = kk * 8;
            uint32_t af[4][4];
#pragma unroll
            for (int mt = 0; mt < 4; mt++) {
                int r = wm + mt * 16 + g;
                af[mt][0] = As[kb + t4][r];
                af[mt][1] = As[kb + t4][r + 8];
                af[mt][2] = As[kb + t4 + 4][r];
                af[mt][3] = As[kb + t4 + 4][r + 8];
            }
#pragma unroll
            for (int nt = 0; nt < 4; nt++) {
                int cn = wn + nt * 8 + g;
                uint32_t b0 = Bs[kb + t4][cn];
                uint32_t b1 = Bs[kb + t4 + 4][cn];
#pragma unroll
                for (int mt = 0; mt < 4; mt++)
                    mma_bf16(acc[mt][nt], af[mt][0], af[mt][1], af[mt][2], af[mt][3], b0, b1);
            }
        }
        __syncthreads();
    }

#pragma unroll
    for (int mt = 0; mt < 4; mt++) {
        int r0 = rowBase + wm + mt * 16 + g;
#pragma unroll
        for (int nt = 0; nt < 4; nt++) {
            int col = colBase + wn + nt * 8 + 2 * t4;
            if (r0 < M)
                *(__nv_bfloat162*)(Cb + (size_t)r0 * Ncol + col) =
                    __floats2bfloat162_rn(acc[mt][nt][0], acc[mt][nt][1]);
            if (r0 + 8 < M)
                *(__nv_bfloat162*)(Cb + (size_t)(r0 + 8) * Ncol + col) =
                    __floats2bfloat162_rn(acc[mt][nt][2], acc[mt][nt][3]);
        }
    }
}

// ---------------- helpers ----------------
__device__ __forceinline__ void acc8(uint4 u, float* a) {
    float2 p;
    p = __bfloat1622float2(*reinterpret_cast<__nv_bfloat162*>(&u.x)); a[0] += p.x; a[1] += p.y;
    p = __bfloat1622float2(*reinterpret_cast<__nv_bfloat162*>(&u.y)); a[2] += p.x; a[3] += p.y;
    p = __bfloat1622float2(*reinterpret_cast<__nv_bfloat162*>(&u.z)); a[4] += p.x; a[5] += p.y;
    p = __bfloat1622float2(*reinterpret_cast<__nv_bfloat162*>(&u.w)); a[6] += p.x; a[7] += p.y;
}
__device__ __forceinline__ void unp8(uint4 u, float* f) {
    float2 p;
    p = __bfloat1622float2(*reinterpret_cast<__nv_bfloat162*>(&u.x)); f[0] = p.x; f[1] = p.y;
    p = __bfloat1622float2(*reinterpret_cast<__nv_bfloat162*>(&u.y)); f[2] = p.x; f[3] = p.y;
    p = __bfloat1622float2(*reinterpret_cast<__nv_bfloat162*>(&u.z)); f[4] = p.x; f[5] = p.y;
    p = __bfloat1622float2(*reinterpret_cast<__nv_bfloat162*>(&u.w)); f[6] = p.x; f[7] = p.y;
}

// ---------------- pull-aggregation, layer 0: 2 rows/step, uint4 lanes ----------------
// warp = 1 node; lane = (half, sl): halves fetch rows j / j+1; sl covers 8 cols.
__global__ __launch_bounds__(256)
void agg0_kernel(const float* __restrict__ bl0, const float* __restrict__ bp, int N) {
    int w = (blockIdx.x * blockDim.x + threadIdx.x) >> 5;
    int lane = threadIdx.x & 31;
    int half = lane >> 4;
    int sl = lane & 15;
    if (w >= N) return;
    int nbeg = g_rowptr[w], nend = g_rowptr[w + 1];

    float a[8];
#pragma unroll
    for (int i = 0; i < 8; i++) a[i] = 0.f;

    int j = nbeg;
    for (; j + 4 <= nend; j += 4) {
        int r0 = g_csr_src[j + half];
        int r1 = g_csr_src[j + 2 + half];
        uint4 u0 = *(const uint4*)(g_C1b + (size_t)r0 * 384 + sl * 8);
        uint4 u1 = *(const uint4*)(g_C1b + (size_t)r1 * 384 + sl * 8);
        acc8(u0, a);
        acc8(u1, a);
    }
    for (; j + 2 <= nend; j += 2) {
        int r = g_csr_src[j + half];
        uint4 u = *(const uint4*)(g_C1b + (size_t)r * 384 + sl * 8);
        acc8(u, a);
    }
    if (j < nend && half == 0) {
        int r = g_csr_src[j];
        uint4 u = *(const uint4*)(g_C1b + (size_t)r * 384 + sl * 8);
        acc8(u, a);
    }
#pragma unroll
    for (int i = 0; i < 8; i++) a[i] += __shfl_xor_sync(0xffffffffu, a[i], 16);

    if (half == 0) {
        float dinv = 1.0f / fmaxf((float)(nend - nbeg), 1.0f);
        float r[8], p[8];
        unp8(*(const uint4*)(g_C1b + (size_t)w * 384 + 128 + sl * 8), r);
        unp8(*(const uint4*)(g_C1b + (size_t)w * 384 + 256 + sl * 8), p);
        float4 bl0a = *(const float4*)(bl0 + sl * 8);
        float4 bl0b = *(const float4*)(bl0 + sl * 8 + 4);
        float4 bpa  = *(const float4*)(bp + sl * 8);
        float4 bpb  = *(const float4*)(bp + sl * 8 + 4);
        float blv[8] = {bl0a.x, bl0a.y, bl0a.z, bl0a.w, bl0b.x, bl0b.y, bl0b.z, bl0b.w};
        float bpv[8] = {bpa.x, bpa.y, bpa.z, bpa.w, bpb.x, bpb.y, bpb.z, bpb.w};
        float o[8];
#pragma unroll
        for (int i = 0; i < 8; i++)
            o[i] = fmaxf(fmaf(a[i], dinv, blv[i] + r[i]), 0.f) + p[i] + bpv[i];
        uint4 q;
        __nv_bfloat162 t0 = __floats2bfloat162_rn(o[0], o[1]);
        __nv_bfloat162 t1 = __floats2bfloat162_rn(o[2], o[3]);
        __nv_bfloat162 t2 = __floats2bfloat162_rn(o[4], o[5]);
        __nv_bfloat162 t3 = __floats2bfloat162_rn(o[6], o[7]);
        q.x = *reinterpret_cast<uint32_t*>(&t0); q.y = *reinterpret_cast<uint32_t*>(&t1);
        q.z = *reinterpret_cast<uint32_t*>(&t2); q.w = *reinterpret_cast<uint32_t*>(&t3);
        *(uint4*)(g_h1b + (size_t)w * DH + sl * 8) = q;
    }
}

// ---------------- pull-aggregation, layer 1 ----------------
__global__ __launch_bounds__(256)
void agg1_kernel(const float* __restrict__ bl1, int N) {
    int w = (blockIdx.x * blockDim.x + threadIdx.x) >> 5;
    int lane = threadIdx.x & 31;
    int half = lane >> 4;
    int sl = lane & 15;
    if (w >= N) return;
    int nbeg = g_rowptr[w], nend = g_rowptr[w + 1];

    float a[8];
#pragma unroll
    for (int i = 0; i < 8; i++) a[i] = 0.f;

    int j = nbeg;
    for (; j + 4 <= nend; j += 4) {
        int r0 = g_csr_src[j + half];
        int r1 = g_csr_src[j + 2 + half];
        uint4 u0 = *(const uint4*)(g_C2b + (size_t)r0 * 256 + sl * 8);
        uint4 u1 = *(const uint4*)(g_C2b + (size_t)r1 * 256 + sl * 8);
        acc8(u0, a);
        acc8(u1, a);
    }
    for (; j + 2 <= nend; j += 2) {
        int r = g_csr_src[j + half];
        uint4 u = *(const uint4*)(g_C2b + (size_t)r * 256 + sl * 8);
        acc8(u, a);
    }
    if (j < nend && half == 0) {
        int r = g_csr_src[j];
        uint4 u = *(const uint4*)(g_C2b + (size_t)r * 256 + sl * 8);
        acc8(u, a);
    }
#pragma unroll
    for (int i = 0; i < 8; i++) a[i] += __shfl_xor_sync(0xffffffffu, a[i], 16);

    if (half == 0) {
        float dinv = 1.0f / fmaxf((float)(nend - nbeg), 1.0f);
        float r[8], h[8];
        unp8(*(const uint4*)(g_C2b + (size_t)w * 256 + 128 + sl * 8), r);
        unp8(*(const uint4*)(g_h1b + (size_t)w * DH + sl * 8), h);
        float4 bla = *(const float4*)(bl1 + sl * 8);
        float4 blb = *(const float4*)(bl1 + sl * 8 + 4);
        float blv[8] = {bla.x, bla.y, bla.z, bla.w, blb.x, blb.y, blb.z, blb.w};
        float o[8];
#pragma unroll
        for (int i = 0; i < 8; i++)
            o[i] = fmaxf(fmaf(a[i], dinv, blv[i] + r[i]), 0.f) + h[i];
        uint4 q;
        __nv_bfloat162 t0 = __floats2bfloat162_rn(o[0], o[1]);
        __nv_bfloat162 t1 = __floats2bfloat162_rn(o[2], o[3]);
        __nv_bfloat162 t2 = __floats2bfloat162_rn(o[4], o[5]);
        __nv_bfloat162 t3 = __floats2bfloat162_rn(o[6], o[7]);
        q.x = *reinterpret_cast<uint32_t*>(&t0); q.y = *reinterpret_cast<uint32_t*>(&t1);
        q.z = *reinterpret_cast<uint32_t*>(&t2); q.w = *reinterpret_cast<uint32_t*>(&t3);
        *(uint4*)(g_h2b + (size_t)w * DH + sl * 8) = q;
    }
}

// ---------------- MMA head: gnn = relu(h2b@W1 + b1)@W2 + b2; blend ----------------
__global__ __launch_bounds__(256)
void head_mma(const float* __restrict__ W1, const float* __restrict__ b1,
              const float* __restrict__ W2, const float* __restrict__ b2,
              const float* __restrict__ rer, const float* __restrict__ alogit,
              float* __restrict__ out, int N) {
    extern __shared__ uint32_t sm[];
    uint32_t* As = sm;
    uint32_t* Bs = sm + 9216;
    float* Cs = (float*)sm;
    __shared__ float b1s[64];
    __shared__ float W2s[64];

    const int t = threadIdx.x;
    const int lane = t & 31;
    const int warp = t >> 5;
    const int wm = (warp & 1) * 64;
    const int wn = (warp >> 1) * 16;
    const int g = lane >> 2;
    const int t4 = lane & 3;
    const int rowBase = blockIdx.x * 128;

    for (int idx = t; idx < 64 * 64; idx += 256) {
        int kp = idx >> 6, col = idx & 63;
        __nv_bfloat162 p = __floats2bfloat162_rn(W1[(2 * kp) * 64 + col],
                                                 W1[(2 * kp + 1) * 64 + col]);
        Bs[kp * 72 + col] = *reinterpret_cast<uint32_t*>(&p);
    }
    if (t < 64) { b1s[t] = b1[t]; W2s[t] = W2[t]; }

    {
        int row = t & 127;
        int half = t >> 7;
        bool ok = (rowBase + row) < N;
        const uint4* aRow = (const uint4*)(g_h2b + (size_t)(rowBase + row) * DH);
#pragma unroll
        for (int q = 0; q < 8; q++) {
            uint4 u = ok ? aRow[half * 8 + q] : make_uint4(0, 0, 0, 0);
            int kp = (half * 8 + q) * 4;
            As[(kp + 0) * SPAD + row] = u.x;
            As[(kp + 1) * SPAD + row] = u.y;
            As[(kp + 2) * SPAD + row] = u.z;
            As[(kp + 3) * SPAD + row] = u.w;
        }
    }
    __syncthreads();

    float acc[4][2][4];
#pragma unroll
    for (int mt = 0; mt < 4; mt++)
#pragma unroll
        for (int nt = 0; nt < 2; nt++)
#pragma unroll
            for (int i = 0; i < 4; i++) acc[mt][nt][i] = 0.f;

#pragma unroll
    for (int step = 0; step < 8; step++) {
        const int kb = step * 8;
        uint32_t af[4][4];
#pragma unroll
        for (int mt = 0; mt < 4; mt++) {
            int r = wm + mt * 16 + g;
            af[mt][0] = As[(kb + t4) * SPAD + r];
            af[mt][1] = As[(kb + t4) * SPAD + r + 8];
            af[mt][2] = As[(kb + t4 + 4) * SPAD + r];
            af[mt][3] = As[(kb + t4 + 4) * SPAD + r + 8];
        }
#pragma unroll
        for (int nt = 0; nt < 2; nt++) {
            int cn = wn + nt * 8 + g;
            uint32_t b0 = Bs[(kb + t4) * 72 + cn];
            uint32_t b1r = Bs[(kb + t4 + 4) * 72 + cn];
#pragma unroll
            for (int mt = 0; mt < 4; mt++)
                mma_bf16(acc[mt][nt], af[mt][0], af[mt][1], af[mt][2], af[mt][3], b0, b1r);
        }
    }
    __syncthreads();

#pragma unroll
    for (int mt = 0; mt < 4; mt++) {
        int r = wm + mt * 16 + g;
#pragma unroll
        for (int nt = 0; nt < 2; nt++) {
            int col = wn + nt * 8 + 2 * t4;
            Cs[r * 72 + col]       = acc[mt][nt][0];
            Cs[r * 72 + col + 1]   = acc[mt][nt][1];
            Cs[(r + 8) * 72 + col]     = acc[mt][nt][2];
            Cs[(r + 8) * 72 + col + 1] = acc[mt][nt][3];
        }
    }
    __syncthreads();

    {
        int row = t >> 1;
        int hc = (t & 1) * 32;
        float s = 0.f;
#pragma unroll
        for (int c = 0; c < 32; c++) {
            int col = hc + c;
            s = fmaf(fmaxf(Cs[row * 72 + col] + b1s[col], 0.f), W2s[col], s);
        }
        s += __shfl_xor_sync(0xffffffffu, s, 1);
        int gr = rowBase + row;
        if ((t & 1) == 0 && gr < N) {
            float gnn = s + b2[0];
            float alpha = 1.0f / (1.0f + __expf(-alogit[0]));
            out[gr] = alpha * rer[gr] + (1.0f - alpha) * gnn;
        }
    }
}

// ---------------- launch ----------------
extern "C" void kernel_launch(void* const* d_in, const int* in_sizes, int n_in,
                              void* d_out, int out_size) {
    const float* x     = (const float*)d_in[0];
    const int*   eidx  = (const int*)d_in[1];
    const float* rer   = (const float*)d_in[2];
    const float* Wp    = (const float*)d_in[3];
    const float* bp    = (const float*)d_in[4];
    const float* Wl0   = (const float*)d_in[5];
    const float* bl0   = (const float*)d_in[6];
    const float* Wr0   = (const float*)d_in[7];
    const float* Wl1   = (const float*)d_in[8];
    const float* bl1   = (const float*)d_in[9];
    const float* Wr1   = (const float*)d_in[10];
    const float* W1    = (const float*)d_in[11];
    const float* b1    = (const float*)d_in[12];
    const float* W2    = (const float*)d_in[13];
    const float* b2    = (const float*)d_in[14];
    const float* alog  = (const float*)d_in[15];
    float* out = (float*)d_out;

    const int N = in_sizes[0] / DIN;       // 50000
    const int E = in_sizes[1] / 2;         // 800000
    const int* src = eidx;
    const int* dst = eidx + E;

    __nv_bfloat16 *C1b, *C2b, *xb, *h1b;
    uint32_t *Bp1b, *Bp2b;
    cudaGetSymbolAddress((void**)&C1b,  g_C1b);
    cudaGetSymbolAddress((void**)&C2b,  g_C2b);
    cudaGetSymbolAddress((void**)&xb,   g_xb);
    cudaGetSymbolAddress((void**)&h1b,  g_h1b);
    cudaGetSymbolAddress((void**)&Bp1b, g_Bp1b);
    cudaGetSymbolAddress((void**)&Bp2b, g_Bp2b);

    static int init_done = 0;
    if (!init_done) {
        cudaFuncSetAttribute(head_mma, cudaFuncAttributeMaxDynamicSharedMemorySize, 55296);
        if (!g_s2) {
            cudaStreamCreateWithFlags(&g_s2, cudaStreamNonBlocking);
            cudaEventCreateWithFlags(&g_evFork, cudaEventDisableTiming);
            cudaEventCreateWithFlags(&g_evJoin, cudaEventDisableTiming);
        }
        init_done = 1;
    }

    // ---- fork side stream for CSR build ----
    cudaEventRecord(g_evFork, 0);
    cudaStreamWaitEvent(g_s2, g_evFork, 0);

    zero_deg<<<(N + 255) / 256, 256, 0, g_s2>>>(N);
    hist_kernel<<<(E + 255) / 256, 256, 0, g_s2>>>(dst, E);
    int nb = (N + 1023) / 1024;
    scan_blocks<<<nb, 1024, 0, g_s2>>>(N);
    scan_add_fused<<<(N + 255) / 256, 256, 0, g_s2>>>(N);
    csr_fill<<<(E + 255) / 256, 256, 0, g_s2>>>(src, dst, E);
    cudaEventRecord(g_evJoin, g_s2);

    // ---- main stream: pack, convert, GEMM1 (concurrent with CSR build) ----
    pack_kernel<<<((DIN / 2) * 384 + 255) / 256, 256>>>(Wl0, Wr0, Wp, Wl1, Wr1);
    {
        int nWords = N * DIN / 2;
        convert_x<<<(nWords + 255) / 256, 256>>>(x, nWords);
    }
    {
        dim3 grid(384 / 128, (N + 127) / 128);
        gemm_bf16<<<grid, 256>>>(xb, Bp1b, C1b, N, DIN, 384);
    }

    // ---- join: agg0 needs CSR + GEMM1 ----
    cudaStreamWaitEvent(0, g_evJoin, 0);
    agg0_kernel<<<(N * 32 + 255) / 256, 256>>>(bl0, bp, N);

    // GEMM2
    {
        dim3 grid(256 / 128, (N + 127) / 128);
        gemm_bf16<<<grid, 256>>>(h1b, Bp2b, C2b, N, DH, 256);
    }

    // pull-agg layer 1 + epilogue -> h2 bf16
    agg1_kernel<<<(N * 32 + 255) / 256, 256>>>(bl1, N);

    // MMA head + blend
    head_mma<<<(N + 127) / 128, 256, 55296>>>(W1, b1, W2, b2, rer, alog, out, N);
}

// round 9
// speedup vs baseline: 1.1065x; 1.1065x over previous
#include <cuda_runtime.h>
#include <cuda_bf16.h>
#include <math.h>
#include <stdint.h>

#define NN   50000
#define EE   800000
#define DIN  256
#define DH   128

// ---------------- scratch (static device globals; no allocation) ----------------
__device__ __align__(16) __nv_bfloat16 g_C1b[(size_t)NN * 384];   // bf16: msg | r0 | proj
__device__ __align__(16) __nv_bfloat16 g_C2b[(size_t)NN * 256];   // bf16: msg | r1
__device__ __align__(16) __nv_bfloat16 g_xb [(size_t)NN * DIN];   // x in bf16
__device__ __align__(16) __nv_bfloat16 g_h1b[(size_t)NN * DH];    // h1 in bf16
__device__ __align__(16) __nv_bfloat16 g_h2b[(size_t)NN * DH];    // h2 in bf16
__device__ int g_deg[NN];
__device__ int g_rowptr[NN + 1];
__device__ int g_cursor[NN];
__device__ int g_csr_src[EE];
__device__ int g_bsum[64];
__device__ __align__(16) uint32_t g_Bp1b[(DIN / 2) * 384];        // bf16 pairs [kpair][384]
__device__ __align__(16) uint32_t g_Bp2b[(DH / 2) * 256];         // bf16 pairs [kpair][256]

// ---------------- side-stream resources ----------------
static cudaStream_t g_s2 = nullptr;
static cudaEvent_t  g_evFork = nullptr, g_evJoin = nullptr;
namespace {
struct InitRes {
    InitRes() {
        cudaStreamCreateWithFlags(&g_s2, cudaStreamNonBlocking);
        cudaEventCreateWithFlags(&g_evFork, cudaEventDisableTiming);
        cudaEventCreateWithFlags(&g_evJoin, cudaEventDisableTiming);
    }
};
static InitRes g_initres;
}

// ---------------- pack weights to bf16 k-pair layout ----------------
__global__ void pack_kernel(const float* __restrict__ Wl0, const float* __restrict__ Wr0,
                            const float* __restrict__ Wp,
                            const float* __restrict__ Wl1, const float* __restrict__ Wr1) {
    int idx = blockIdx.x * blockDim.x + threadIdx.x;
    if (idx < (DIN / 2) * 384) {
        int kp = idx / 384, j = idx % 384;
        int k0 = 2 * kp, k1 = 2 * kp + 1;
        float lo, hi;
        if (j < 128)      { lo = Wl0[k0 * DH + j];        hi = Wl0[k1 * DH + j]; }
        else if (j < 256) { lo = Wr0[k0 * DH + j - 128];  hi = Wr0[k1 * DH + j - 128]; }
        else              { lo = Wp [k0 * DH + j - 256];  hi = Wp [k1 * DH + j - 256]; }
        __nv_bfloat162 p = __floats2bfloat162_rn(lo, hi);
        g_Bp1b[idx] = *reinterpret_cast<uint32_t*>(&p);
    }
    if (idx < (DH / 2) * 256) {
        int kp = idx / 256, j = idx % 256;
        int k0 = 2 * kp, k1 = 2 * kp + 1;
        float lo, hi;
        if (j < 128) { lo = Wl1[k0 * DH + j];       hi = Wl1[k1 * DH + j]; }
        else         { lo = Wr1[k0 * DH + j - 128]; hi = Wr1[k1 * DH + j - 128]; }
        __nv_bfloat162 p = __floats2bfloat162_rn(lo, hi);
        g_Bp2b[idx] = *reinterpret_cast<uint32_t*>(&p);
    }
}

// ---------------- x -> bf16 ----------------
__global__ void convert_x(const float* __restrict__ x, int nWords) {
    int i = blockIdx.x * blockDim.x + threadIdx.x;
    if (i >= nWords) return;
    float2 v = ((const float2*)x)[i];
    __nv_bfloat162 p = __floats2bfloat162_rn(v.x, v.y);
    ((uint32_t*)g_xb)[i] = *reinterpret_cast<uint32_t*>(&p);
}

// ---------------- CSR build chain (side stream) ----------------
__global__ void zero_deg(int N) {
    int i = blockIdx.x * blockDim.x + threadIdx.x;
    if (i < N) g_deg[i] = 0;
}

__global__ void hist_kernel(const int* __restrict__ dst, int E) {
    int e = blockIdx.x * blockDim.x + threadIdx.x;
    if (e < E) atomicAdd(&g_deg[dst[e]], 1);
}

__global__ __launch_bounds__(1024)
void scan_blocks(int N) {
    __shared__ int wsum[32];
    int lane = threadIdx.x & 31, wid = threadIdx.x >> 5;
    int idx = blockIdx.x * 1024 + threadIdx.x;
    int v = (idx < N) ? g_deg[idx] : 0;
    int x = v;
#pragma unroll
    for (int o = 1; o < 32; o <<= 1) {
        int y = __shfl_up_sync(0xffffffffu, x, o);
        if (lane >= o) x += y;
    }
    if (lane == 31) wsum[wid] = x;
    __syncthreads();
    if (wid == 0) {
        int s = wsum[lane];
#pragma unroll
        for (int o = 1; o < 32; o <<= 1) {
            int y = __shfl_up_sync(0xffffffffu, s, o);
            if (lane >= o) s += y;
        }
        wsum[lane] = s;
    }
    __syncthreads();
    int excl = x - v + (wid > 0 ? wsum[wid - 1] : 0);
    if (idx < N) g_rowptr[idx] = excl;
    if (threadIdx.x == 1023) g_bsum[blockIdx.x] = excl + v;
}

__global__ void scan_add_fused(int N) {
    __shared__ int pre_s;
    int grp = blockIdx.x >> 2;
    if (threadIdx.x < 32) {
        int s = 0;
        for (int g = threadIdx.x; g < grp; g += 32) s += g_bsum[g];
#pragma unroll
        for (int o = 16; o; o >>= 1) s += __shfl_xor_sync(0xffffffffu, s, o);
        if (threadIdx.x == 0) pre_s = s;
    }
    __syncthreads();
    int i = blockIdx.x * 256 + threadIdx.x;
    if (i < N) {
        int r = g_rowptr[i] + pre_s;
        g_rowptr[i] = r;
        g_cursor[i] = r;
        if (i == N - 1) g_rowptr[N] = r + g_deg[N - 1];
    }
}

__global__ void csr_fill(const int* __restrict__ src, const int* __restrict__ dst, int E) {
    int e = blockIdx.x * blockDim.x + threadIdx.x;
    if (e >= E) return;
    int slot = atomicAdd(&g_cursor[dst[e]], 1);
    g_csr_src[slot] = src[e];
}

// ---------------- bf16 tensor-core GEMM (m16n8k16), bf16 output ----------------
#define SPAD 136

__device__ __forceinline__ void mma_bf16(float c[4], uint32_t a0, uint32_t a1,
                                         uint32_t a2, uint32_t a3,
                                         uint32_t b0, uint32_t b1) {
    asm volatile(
        "mma.sync.aligned.m16n8k16.row.col.f32.bf16.bf16.f32 "
        "{%0,%1,%2,%3}, {%4,%5,%6,%7}, {%8,%9}, {%0,%1,%2,%3};"
        : "+f"(c[0]), "+f"(c[1]), "+f"(c[2]), "+f"(c[3])
        : "r"(a0), "r"(a1), "r"(a2), "r"(a3), "r"(b0), "r"(b1));
}

__global__ __launch_bounds__(256)
void gemm_bf16(const __nv_bfloat16* __restrict__ A, const uint32_t* __restrict__ Bp,
               __nv_bfloat16* __restrict__ Cb, int M, int K, int Ncol) {
    __shared__ uint32_t As[16][SPAD];
    __shared__ uint32_t Bs[16][SPAD];

    const int t = threadIdx.x;
    const int lane = t & 31;
    const int warp = t >> 5;
    const int wm = (warp & 1) * 64;
    const int wn = (warp >> 1) * 32;
    const int g = lane >> 2;
    const int t4 = lane & 3;

    const int rowBase = blockIdx.y * 128;
    const int colBase = blockIdx.x * 128;

    const int ar = t & 127;
    const int ah = t >> 7;
    const int bkp = t >> 4;
    const int bcol = (t & 15) * 8;

    float acc[4][4][4];
#pragma unroll
    for (int mt = 0; mt < 4; mt++)
#pragma unroll
        for (int nt = 0; nt < 4; nt++)
#pragma unroll
            for (int i = 0; i < 4; i++) acc[mt][nt][i] = 0.f;

    const int grow = rowBase + ar;
    const bool arow_ok = (grow < M);
    const __nv_bfloat16* aBase = A + (size_t)grow * K + ah * 16;
    const uint32_t* bBase = Bp + (size_t)bkp * Ncol + colBase + bcol;

    uint4 ra0, ra1, rb0, rb1;

    if (arow_ok) {
        ra0 = *(const uint4*)(aBase);
        ra1 = *(const uint4*)(aBase + 8);
    } else {
        ra0 = make_uint4(0, 0, 0, 0); ra1 = make_uint4(0, 0, 0, 0);
    }
    rb0 = *(const uint4*)(bBase);
    rb1 = *(const uint4*)(bBase + 4);

    const int nChunks = K >> 5;
    for (int ci = 0; ci < nChunks; ci++) {
        {
            const int kb = ah * 8;
            As[kb + 0][ar] = ra0.x; As[kb + 1][ar] = ra0.y;
            As[kb + 2][ar] = ra0.z; As[kb + 3][ar] = ra0.w;
            As[kb + 4][ar] = ra1.x; As[kb + 5][ar] = ra1.y;
            As[kb + 6][ar] = ra1.z; As[kb + 7][ar] = ra1.w;
            *(uint4*)&Bs[bkp][bcol]     = rb0;
            *(uint4*)&Bs[bkp][bcol + 4] = rb1;
        }
        __syncthreads();

        if (ci + 1 < nChunks) {
            int k0 = (ci + 1) << 5;
            if (arow_ok) {
                ra0 = *(const uint4*)(aBase + k0);
                ra1 = *(const uint4*)(aBase + k0 + 8);
            }
            rb0 = *(const uint4*)(bBase + (size_t)(k0 >> 1) * Ncol);
            rb1 = *(const uint4*)(bBase + (size_t)(k0 >> 1) * Ncol + 4);
        }

#pragma unroll
        for (int kk = 0; kk < 2; kk++) {
            const int kb = kk * 8;
            uint32_t af[4][4];
#pragma unroll
            for (int mt = 0; mt < 4; mt++) {
                int r = wm + mt * 16 + g;
                af[mt][0] = As[kb + t4][r];
                af[mt][1] = As[kb + t4][r + 8];
                af[mt][2] = As[kb + t4 + 4][r];
                af[mt][3] = As[kb + t4 + 4][r + 8];
            }
#pragma unroll
            for (int nt = 0; nt < 4; nt++) {
                int cn = wn + nt * 8 + g;
                uint32_t b0 = Bs[kb + t4][cn];
                uint32_t b1 = Bs[kb + t4 + 4][cn];
#pragma unroll
                for (int mt = 0; mt < 4; mt++)
                    mma_bf16(acc[mt][nt], af[mt][0], af[mt][1], af[mt][2], af[mt][3], b0, b1);
            }
        }
        __syncthreads();
    }

#pragma unroll
    for (int mt = 0; mt < 4; mt++) {
        int r0 = rowBase + wm + mt * 16 + g;
#pragma unroll
        for (int nt = 0; nt < 4; nt++) {
            int col = colBase + wn + nt * 8 + 2 * t4;
            if (r0 < M)
                *(__nv_bfloat162*)(Cb + (size_t)r0 * Ncol + col) =
                    __floats2bfloat162_rn(acc[mt][nt][0], acc[mt][nt][1]);
            if (r0 + 8 < M)
                *(__nv_bfloat162*)(Cb + (size_t)(r0 + 8) * Ncol + col) =
                    __floats2bfloat162_rn(acc[mt][nt][2], acc[mt][nt][3]);
        }
    }
}

// ---------------- bf16x4 -> 4 floats helper ----------------
__device__ __forceinline__ void bf4(uint2 u, float& f0, float& f1, float& f2, float& f3) {
    float2 p0 = __bfloat1622float2(*reinterpret_cast<__nv_bfloat162*>(&u.x));
    float2 p1 = __bfloat1622float2(*reinterpret_cast<__nv_bfloat162*>(&u.y));
    f0 = p0.x; f1 = p0.y; f2 = p1.x; f3 = p1.y;
}
__device__ __forceinline__ void acc4(uint2 u, float& a0, float& a1, float& a2, float& a3) {
    float f0, f1, f2, f3;
    bf4(u, f0, f1, f2, f3);
    a0 += f0; a1 += f1; a2 += f2; a3 += f3;
}

// ---------------- pull-aggregation, layer 0: uint2 lanes, 8-row unroll ----------------
__global__ __launch_bounds__(256)
void agg0_kernel(const float* __restrict__ bl0, const float* __restrict__ bp, int N) {
    int w = (blockIdx.x * blockDim.x + threadIdx.x) >> 5;
    int lane = threadIdx.x & 31;
    if (w >= N) return;
    int nbeg = g_rowptr[w], nend = g_rowptr[w + 1];
    float a0 = 0.f, a1 = 0.f, a2 = 0.f, a3 = 0.f;
    int j = nbeg;
    // 8 rows per iteration: 8 independent loads in flight
    for (; j + 8 <= nend; j += 8) {
        uint2 v0 = *((const uint2*)(g_C1b + (size_t)g_csr_src[j + 0] * 384) + lane);
        uint2 v1 = *((const uint2*)(g_C1b + (size_t)g_csr_src[j + 1] * 384) + lane);
        uint2 v2 = *((const uint2*)(g_C1b + (size_t)g_csr_src[j + 2] * 384) + lane);
        uint2 v3 = *((const uint2*)(g_C1b + (size_t)g_csr_src[j + 3] * 384) + lane);
        uint2 v4 = *((const uint2*)(g_C1b + (size_t)g_csr_src[j + 4] * 384) + lane);
        uint2 v5 = *((const uint2*)(g_C1b + (size_t)g_csr_src[j + 5] * 384) + lane);
        uint2 v6 = *((const uint2*)(g_C1b + (size_t)g_csr_src[j + 6] * 384) + lane);
        uint2 v7 = *((const uint2*)(g_C1b + (size_t)g_csr_src[j + 7] * 384) + lane);
        acc4(v0, a0, a1, a2, a3); acc4(v1, a0, a1, a2, a3);
        acc4(v2, a0, a1, a2, a3); acc4(v3, a0, a1, a2, a3);
        acc4(v4, a0, a1, a2, a3); acc4(v5, a0, a1, a2, a3);
        acc4(v6, a0, a1, a2, a3); acc4(v7, a0, a1, a2, a3);
    }
    for (; j + 4 <= nend; j += 4) {
        uint2 v0 = *((const uint2*)(g_C1b + (size_t)g_csr_src[j + 0] * 384) + lane);
        uint2 v1 = *((const uint2*)(g_C1b + (size_t)g_csr_src[j + 1] * 384) + lane);
        uint2 v2 = *((const uint2*)(g_C1b + (size_t)g_csr_src[j + 2] * 384) + lane);
        uint2 v3 = *((const uint2*)(g_C1b + (size_t)g_csr_src[j + 3] * 384) + lane);
        acc4(v0, a0, a1, a2, a3); acc4(v1, a0, a1, a2, a3);
        acc4(v2, a0, a1, a2, a3); acc4(v3, a0, a1, a2, a3);
    }
    for (; j < nend; j++) {
        uint2 v = *((const uint2*)(g_C1b + (size_t)g_csr_src[j] * 384) + lane);
        acc4(v, a0, a1, a2, a3);
    }
    float dinv = 1.0f / fmaxf((float)(nend - nbeg), 1.0f);
    float r0, r1, r2, r3, p0, p1, p2, p3;
    bf4(*(const uint2*)(g_C1b + (size_t)w * 384 + 128 + lane * 4), r0, r1, r2, r3);
    bf4(*(const uint2*)(g_C1b + (size_t)w * 384 + 256 + lane * 4), p0, p1, p2, p3);
    float4 bl = *(const float4*)(bl0 + lane * 4);
    float4 bv = *(const float4*)(bp + lane * 4);
    float o0 = fmaxf(fmaf(a0, dinv, bl.x + r0), 0.f) + p0 + bv.x;
    float o1 = fmaxf(fmaf(a1, dinv, bl.y + r1), 0.f) + p1 + bv.y;
    float o2 = fmaxf(fmaf(a2, dinv, bl.z + r2), 0.f) + p2 + bv.z;
    float o3 = fmaxf(fmaf(a3, dinv, bl.w + r3), 0.f) + p3 + bv.w;
    __nv_bfloat162 q0 = __floats2bfloat162_rn(o0, o1);
    __nv_bfloat162 q1 = __floats2bfloat162_rn(o2, o3);
    uint2 qo; qo.x = *reinterpret_cast<uint32_t*>(&q0); qo.y = *reinterpret_cast<uint32_t*>(&q1);
    *((uint2*)(g_h1b + (size_t)w * DH) + lane) = qo;
}

// ---------------- pull-aggregation, layer 1: uint2 lanes, 8-row unroll ----------------
__global__ __launch_bounds__(256)
void agg1_kernel(const float* __restrict__ bl1, int N) {
    int w = (blockIdx.x * blockDim.x + threadIdx.x) >> 5;
    int lane = threadIdx.x & 31;
    if (w >= N) return;
    int nbeg = g_rowptr[w], nend = g_rowptr[w + 1];
    float a0 = 0.f, a1 = 0.f, a2 = 0.f, a3 = 0.f;
    int j = nbeg;
    for (; j + 8 <= nend; j += 8) {
        uint2 v0 = *((const uint2*)(g_C2b + (size_t)g_csr_src[j + 0] * 256) + lane);
        uint2 v1 = *((const uint2*)(g_C2b + (size_t)g_csr_src[j + 1] * 256) + lane);
        uint2 v2 = *((const uint2*)(g_C2b + (size_t)g_csr_src[j + 2] * 256) + lane);
        uint2 v3 = *((const uint2*)(g_C2b + (size_t)g_csr_src[j + 3] * 256) + lane);
        uint2 v4 = *((const uint2*)(g_C2b + (size_t)g_csr_src[j + 4] * 256) + lane);
        uint2 v5 = *((const uint2*)(g_C2b + (size_t)g_csr_src[j + 5] * 256) + lane);
        uint2 v6 = *((const uint2*)(g_C2b + (size_t)g_csr_src[j + 6] * 256) + lane);
        uint2 v7 = *((const uint2*)(g_C2b + (size_t)g_csr_src[j + 7] * 256) + lane);
        acc4(v0, a0, a1, a2, a3); acc4(v1, a0, a1, a2, a3);
        acc4(v2, a0, a1, a2, a3); acc4(v3, a0, a1, a2, a3);
        acc4(v4, a0, a1, a2, a3); acc4(v5, a0, a1, a2, a3);
        acc4(v6, a0, a1, a2, a3); acc4(v7, a0, a1, a2, a3);
    }
    for (; j + 4 <= nend; j += 4) {
        uint2 v0 = *((const uint2*)(g_C2b + (size_t)g_csr_src[j + 0] * 256) + lane);
        uint2 v1 = *((const uint2*)(g_C2b + (size_t)g_csr_src[j + 1] * 256) + lane);
        uint2 v2 = *((const uint2*)(g_C2b + (size_t)g_csr_src[j + 2] * 256) + lane);
        uint2 v3 = *((const uint2*)(g_C2b + (size_t)g_csr_src[j + 3] * 256) + lane);
        acc4(v0, a0, a1, a2, a3); acc4(v1, a0, a1, a2, a3);
        acc4(v2, a0, a1, a2, a3); acc4(v3, a0, a1, a2, a3);
    }
    for (; j < nend; j++) {
        uint2 v = *((const uint2*)(g_C2b + (size_t)g_csr_src[j] * 256) + lane);
        acc4(v, a0, a1, a2, a3);
    }
    float dinv = 1.0f / fmaxf((float)(nend - nbeg), 1.0f);
    float r0, r1, r2, r3, h0, h1, h2, h3;
    bf4(*(const uint2*)(g_C2b + (size_t)w * 256 + 128 + lane * 4), r0, r1, r2, r3);
    bf4(*((const uint2*)(g_h1b + (size_t)w * DH) + lane), h0, h1, h2, h3);
    float4 bl = *(const float4*)(bl1 + lane * 4);
    float o0 = fmaxf(fmaf(a0, dinv, bl.x + r0), 0.f) + h0;
    float o1 = fmaxf(fmaf(a1, dinv, bl.y + r1), 0.f) + h1;
    float o2 = fmaxf(fmaf(a2, dinv, bl.z + r2), 0.f) + h2;
    float o3 = fmaxf(fmaf(a3, dinv, bl.w + r3), 0.f) + h3;
    __nv_bfloat162 q0 = __floats2bfloat162_rn(o0, o1);
    __nv_bfloat162 q1 = __floats2bfloat162_rn(o2, o3);
    uint2 qo; qo.x = *reinterpret_cast<uint32_t*>(&q0); qo.y = *reinterpret_cast<uint32_t*>(&q1);
    *((uint2*)(g_h2b + (size_t)w * DH) + lane) = qo;
}

// ---------------- MMA head: gnn = relu(h2b@W1 + b1)@W2 + b2; blend ----------------
__global__ __launch_bounds__(256)
void head_mma(const float* __restrict__ W1, const float* __restrict__ b1,
              const float* __restrict__ W2, const float* __restrict__ b2,
              const float* __restrict__ rer, const float* __restrict__ alogit,
              float* __restrict__ out, int N) {
    extern __shared__ uint32_t sm[];
    uint32_t* As = sm;
    uint32_t* Bs = sm + 9216;
    float* Cs = (float*)sm;
    __shared__ float b1s[64];
    __shared__ float W2s[64];

    const int t = threadIdx.x;
    const int lane = t & 31;
    const int warp = t >> 5;
    const int wm = (warp & 1) * 64;
    const int wn = (warp >> 1) * 16;
    const int g = lane >> 2;
    const int t4 = lane & 3;
    const int rowBase = blockIdx.x * 128;

    for (int idx = t; idx < 64 * 64; idx += 256) {
        int kp = idx >> 6, col = idx & 63;
        __nv_bfloat162 p = __floats2bfloat162_rn(W1[(2 * kp) * 64 + col],
                                                 W1[(2 * kp + 1) * 64 + col]);
        Bs[kp * 72 + col] = *reinterpret_cast<uint32_t*>(&p);
    }
    if (t < 64) { b1s[t] = b1[t]; W2s[t] = W2[t]; }

    {
        int row = t & 127;
        int half = t >> 7;
        bool ok = (rowBase + row) < N;
        const uint4* aRow = (const uint4*)(g_h2b + (size_t)(rowBase + row) * DH);
#pragma unroll
        for (int q = 0; q < 8; q++) {
            uint4 u = ok ? aRow[half * 8 + q] : make_uint4(0, 0, 0, 0);
            int kp = (half * 8 + q) * 4;
            As[(kp + 0) * SPAD + row] = u.x;
            As[(kp + 1) * SPAD + row] = u.y;
            As[(kp + 2) * SPAD + row] = u.z;
            As[(kp + 3) * SPAD + row] = u.w;
        }
    }
    __syncthreads();

    float acc[4][2][4];
#pragma unroll
    for (int mt = 0; mt < 4; mt++)
#pragma unroll
        for (int nt = 0; nt < 2; nt++)
#pragma unroll
            for (int i = 0; i < 4; i++) acc[mt][nt][i] = 0.f;

#pragma unroll
    for (int step = 0; step < 8; step++) {
        const int kb = step * 8;
        uint32_t af[4][4];
#pragma unroll
        for (int mt = 0; mt < 4; mt++) {
            int r = wm + mt * 16 + g;
            af[mt][0] = As[(kb + t4) * SPAD + r];
            af[mt][1] = As[(kb + t4) * SPAD + r + 8];
            af[mt][2] = As[(kb + t4 + 4) * SPAD + r];
            af[mt][3] = As[(kb + t4 + 4) * SPAD + r + 8];
        }
#pragma unroll
        for (int nt = 0; nt < 2; nt++) {
            int cn = wn + nt * 8 + g;
            uint32_t b0 = Bs[(kb + t4) * 72 + cn];
            uint32_t b1r = Bs[(kb + t4 + 4) * 72 + cn];
#pragma unroll
            for (int mt = 0; mt < 4; mt++)
                mma_bf16(acc[mt][nt], af[mt][0], af[mt][1], af[mt][2], af[mt][3], b0, b1r);
        }
    }
    __syncthreads();

#pragma unroll
    for (int mt = 0; mt < 4; mt++) {
        int r = wm + mt * 16 + g;
#pragma unroll
        for (int nt = 0; nt < 2; nt++) {
            int col = wn + nt * 8 + 2 * t4;
            Cs[r * 72 + col]       = acc[mt][nt][0];
            Cs[r * 72 + col + 1]   = acc[mt][nt][1];
            Cs[(r + 8) * 72 + col]     = acc[mt][nt][2];
            Cs[(r + 8) * 72 + col + 1] = acc[mt][nt][3];
        }
    }
    __syncthreads();

    {
        int row = t >> 1;
        int hc = (t & 1) * 32;
        float s = 0.f;
#pragma unroll
        for (int c = 0; c < 32; c++) {
            int col = hc + c;
            s = fmaf(fmaxf(Cs[row * 72 + col] + b1s[col], 0.f), W2s[col], s);
        }
        s += __shfl_xor_sync(0xffffffffu, s, 1);
        int gr = rowBase + row;
        if ((t & 1) == 0 && gr < N) {
            float gnn = s + b2[0];
            float alpha = 1.0f / (1.0f + __expf(-alogit[0]));
            out[gr] = alpha * rer[gr] + (1.0f - alpha) * gnn;
        }
    }
}

// ---------------- launch ----------------
extern "C" void kernel_launch(void* const* d_in, const int* in_sizes, int n_in,
                              void* d_out, int out_size) {
    const float* x     = (const float*)d_in[0];
    const int*   eidx  = (const int*)d_in[1];
    const float* rer   = (const float*)d_in[2];
    const float* Wp    = (const float*)d_in[3];
    const float* bp    = (const float*)d_in[4];
    const float* Wl0   = (const float*)d_in[5];
    const float* bl0   = (const float*)d_in[6];
    const float* Wr0   = (const float*)d_in[7];
    const float* Wl1   = (const float*)d_in[8];
    const float* bl1   = (const float*)d_in[9];
    const float* Wr1   = (const float*)d_in[10];
    const float* W1    = (const float*)d_in[11];
    const float* b1    = (const float*)d_in[12];
    const float* W2    = (const float*)d_in[13];
    const float* b2    = (const float*)d_in[14];
    const float* alog  = (const float*)d_in[15];
    float* out = (float*)d_out;

    const int N = in_sizes[0] / DIN;       // 50000
    const int E = in_sizes[1] / 2;         // 800000
    const int* src = eidx;
    const int* dst = eidx + E;

    __nv_bfloat16 *C1b, *C2b, *xb, *h1b;
    uint32_t *Bp1b, *Bp2b;
    cudaGetSymbolAddress((void**)&C1b,  g_C1b);
    cudaGetSymbolAddress((void**)&C2b,  g_C2b);
    cudaGetSymbolAddress((void**)&xb,   g_xb);
    cudaGetSymbolAddress((void**)&h1b,  g_h1b);
    cudaGetSymbolAddress((void**)&Bp1b, g_Bp1b);
    cudaGetSymbolAddress((void**)&Bp2b, g_Bp2b);

    static int init_done = 0;
    if (!init_done) {
        cudaFuncSetAttribute(head_mma, cudaFuncAttributeMaxDynamicSharedMemorySize, 55296);
        if (!g_s2) {
            cudaStreamCreateWithFlags(&g_s2, cudaStreamNonBlocking);
            cudaEventCreateWithFlags(&g_evFork, cudaEventDisableTiming);
            cudaEventCreateWithFlags(&g_evJoin, cudaEventDisableTiming);
        }
        init_done = 1;
    }

    // ---- fork side stream for CSR build ----
    cudaEventRecord(g_evFork, 0);
    cudaStreamWaitEvent(g_s2, g_evFork, 0);

    zero_deg<<<(N + 255) / 256, 256, 0, g_s2>>>(N);
    hist_kernel<<<(E + 255) / 256, 256, 0, g_s2>>>(dst, E);
    int nb = (N + 1023) / 1024;
    scan_blocks<<<nb, 1024, 0, g_s2>>>(N);
    scan_add_fused<<<(N + 255) / 256, 256, 0, g_s2>>>(N);
    csr_fill<<<(E + 255) / 256, 256, 0, g_s2>>>(src, dst, E);
    cudaEventRecord(g_evJoin, g_s2);

    // ---- main stream: pack, convert, GEMM1 (concurrent with CSR build) ----
    pack_kernel<<<((DIN / 2) * 384 + 255) / 256, 256>>>(Wl0, Wr0, Wp, Wl1, Wr1);
    {
        int nWords = N * DIN / 2;
        convert_x<<<(nWords + 255) / 256, 256>>>(x, nWords);
    }
    {
        dim3 grid(384 / 128, (N + 127) / 128);
        gemm_bf16<<<grid, 256>>>(xb, Bp1b, C1b, N, DIN, 384);
    }

    // ---- join: agg0 needs CSR + GEMM1 ----
    cudaStreamWaitEvent(0, g_evJoin, 0);
    agg0_kernel<<<(N * 32 + 255) / 256, 256>>>(bl0, bp, N);

    // GEMM2
    {
        dim3 grid(256 / 128, (N + 127) / 128);
        gemm_bf16<<<grid, 256>>>(h1b, Bp2b, C2b, N, DH, 256);
    }

    // pull-agg layer 1 + epilogue -> h2 bf16
    agg1_kernel<<<(N * 32 + 255) / 256, 256>>>(bl1, N);

    // MMA head + blend
    head_mma<<<(N + 127) / 128, 256, 55296>>>(W1, b1, W2, b2, rer, alog, out, N);
}